// round 4
// baseline (speedup 1.0000x reference)
#include <cuda_runtime.h>
#include <cstddef>

#define AN 8192          // sequence length
#define AC 256           // channels
#define AH 4             // heads
#define AD 64            // head dim
#define AC2 512          // 2*C

typedef unsigned long long ull;

// ---------------- packed f32x2 helpers ----------------
__device__ __forceinline__ ull fma2(ull a, ull b, ull c) {
    ull d;
    asm("fma.rn.f32x2 %0, %1, %2, %3;" : "=l"(d) : "l"(a), "l"(b), "l"(c));
    return d;
}
__device__ __forceinline__ ull add2(ull a, ull b) {
    ull d;
    asm("add.rn.f32x2 %0, %1, %2;" : "=l"(d) : "l"(a), "l"(b));
    return d;
}
__device__ __forceinline__ ull pack2(float x, float y) {
    ull r;
    asm("mov.b64 %0, {%1, %2};" : "=l"(r) : "f"(x), "f"(y));
    return r;
}
__device__ __forceinline__ void unpack2(ull v, float& x, float& y) {
    asm("mov.b64 {%0, %1}, %2;" : "=f"(x), "=f"(y) : "l"(v));
}
__device__ __forceinline__ float ex2(float x) {
    float y;
    asm("ex2.approx.f32 %0, %1;" : "=f"(y) : "f"(x));
    return y;
}
__device__ __forceinline__ unsigned smem_u32(const void* p) {
    unsigned r;
    asm("{.reg .u64 t; cvta.to.shared.u64 t, %1; cvt.u32.u64 %0, t;}" : "=r"(r) : "l"(p));
    return r;
}
#define CPASYNC16(dst, src) \
    asm volatile("cp.async.cg.shared.global [%0], [%1], 16;" :: "r"(dst), "l"(src))
#define CPASYNC_COMMIT() asm volatile("cp.async.commit_group;" ::: "memory")
#define CPASYNC_WAIT0()  asm volatile("cp.async.wait_group 0;" ::: "memory")

// ---------------- scratch (allocation-free, device globals) ----------------
__device__ float g_XM[(size_t)AC2 * AN];      // rows 0..255: X = descs^T ; rows 256..511: Wm@msg
__device__ float g_Q[(size_t)AH * AN * AD];   // [h][n][d]
__device__ float g_K[(size_t)AH * AN * AD];
__device__ float g_V[(size_t)AH * AN * AD];
__device__ float g_Msg[(size_t)AC * AN];      // attention output, channel-major [c][n]
__device__ float g_Y[(size_t)AC2 * AN];       // after W1 (then normed in place)
__device__ float g_Z[(size_t)AC * AN];        // after W2

// ---------------- transpose: X[c][n] = descs[n][c] ----------------
__global__ __launch_bounds__(256) void transpose_in(const float* __restrict__ descs,
                                                    float* __restrict__ X) {
    __shared__ float tile[32][33];
    int n0 = blockIdx.x * 32, c0 = blockIdx.y * 32;
    int tx = threadIdx.x, ty = threadIdx.y;
#pragma unroll
    for (int r = 0; r < 4; r++) {
        int n = n0 + ty + r * 8;
        tile[ty + r * 8][tx] = descs[(size_t)n * AC + c0 + tx];
    }
    __syncthreads();
#pragma unroll
    for (int r = 0; r < 4; r++) {
        int c = c0 + ty + r * 8;
        X[(size_t)c * AN + n0 + tx] = tile[tx][ty + r * 8];
    }
}

// ---------------- out[n][c] = descs[n][c] + Z[c][n] ----------------
__global__ __launch_bounds__(256) void transpose_add(const float* __restrict__ descs,
                                                     const float* __restrict__ Z,
                                                     float* __restrict__ out) {
    __shared__ float tile[32][33];
    int n0 = blockIdx.x * 32, c0 = blockIdx.y * 32;
    int tx = threadIdx.x, ty = threadIdx.y;
#pragma unroll
    for (int r = 0; r < 4; r++) {
        int c = c0 + ty + r * 8;
        tile[ty + r * 8][tx] = Z[(size_t)c * AN + n0 + tx];
    }
    __syncthreads();
#pragma unroll
    for (int r = 0; r < 4; r++) {
        int n = n0 + ty + r * 8;
        size_t idx = (size_t)n * AC + c0 + tx;
        out[idx] = descs[idx] + tile[tx][ty + r * 8];
    }
}

// ---------------- fp32 GEMM: C = A[M,K] @ B[K,N] + bias ----------------
template <int OUTMODE>
__global__ __launch_bounds__(256) void gemm_k(const float* __restrict__ A,
                                              const float* __restrict__ B,
                                              const float* __restrict__ bias,
                                              float* __restrict__ C,
                                              int M, int Nn, int K) {
    __shared__ __align__(16) float As[2][16][64];   // As[buf][k][m]
    __shared__ __align__(16) float Bs[2][16][64];   // Bs[buf][k][n]
    int tid = threadIdx.x;
    int n0 = blockIdx.x * 64;
    int m0 = blockIdx.y * 64;
    int tx = tid & 15, ty = tid >> 4;
    int ar = tid >> 2, ac4 = tid & 3;
    int br = tid >> 4, bc4 = tid & 15;

    ull acc2[4][2];
#pragma unroll
    for (int i = 0; i < 4; i++) { acc2[i][0] = 0ull; acc2[i][1] = 0ull; }

    {
        float4 a = *(const float4*)&A[(size_t)(m0 + ar) * K + ac4 * 4];
        float4 b = *(const float4*)&B[(size_t)br * Nn + n0 + bc4 * 4];
        As[0][ac4 * 4 + 0][ar] = a.x;
        As[0][ac4 * 4 + 1][ar] = a.y;
        As[0][ac4 * 4 + 2][ar] = a.z;
        As[0][ac4 * 4 + 3][ar] = a.w;
        *(float4*)&Bs[0][br][bc4 * 4] = b;
    }
    __syncthreads();

    int nIter = K >> 4;
    for (int it = 0; it < nIter; it++) {
        int cur = it & 1;
        float4 an, bn;
        bool has_next = (it + 1 < nIter);
        if (has_next) {
            int k0 = (it + 1) << 4;
            an = *(const float4*)&A[(size_t)(m0 + ar) * K + k0 + ac4 * 4];
            bn = *(const float4*)&B[(size_t)(k0 + br) * Nn + n0 + bc4 * 4];
        }
#pragma unroll
        for (int kk = 0; kk < 16; kk++) {
            float4 av = *(const float4*)&As[cur][kk][ty * 4];
            ulonglong2 bb = *(const ulonglong2*)&Bs[cur][kk][tx * 4];
            ull a0 = pack2(av.x, av.x);
            ull a1 = pack2(av.y, av.y);
            ull a2 = pack2(av.z, av.z);
            ull a3 = pack2(av.w, av.w);
            acc2[0][0] = fma2(a0, bb.x, acc2[0][0]);
            acc2[0][1] = fma2(a0, bb.y, acc2[0][1]);
            acc2[1][0] = fma2(a1, bb.x, acc2[1][0]);
            acc2[1][1] = fma2(a1, bb.y, acc2[1][1]);
            acc2[2][0] = fma2(a2, bb.x, acc2[2][0]);
            acc2[2][1] = fma2(a2, bb.y, acc2[2][1]);
            acc2[3][0] = fma2(a3, bb.x, acc2[3][0]);
            acc2[3][1] = fma2(a3, bb.y, acc2[3][1]);
        }
        if (has_next) {
            int nxt = cur ^ 1;
            As[nxt][ac4 * 4 + 0][ar] = an.x;
            As[nxt][ac4 * 4 + 1][ar] = an.y;
            As[nxt][ac4 * 4 + 2][ar] = an.z;
            As[nxt][ac4 * 4 + 3][ar] = an.w;
            *(float4*)&Bs[nxt][br][bc4 * 4] = bn;
            __syncthreads();
        }
    }

#pragma unroll
    for (int i = 0; i < 4; i++) {
        int m = m0 + ty * 4 + i;
        float bv = bias[m];
        float c0, c1, c2, c3;
        unpack2(acc2[i][0], c0, c1);
        unpack2(acc2[i][1], c2, c3);
        float vals[4] = {c0 + bv, c1 + bv, c2 + bv, c3 + bv};
#pragma unroll
        for (int j = 0; j < 4; j++) {
            int n = n0 + tx * 4 + j;
            if (OUTMODE == 0) {
                C[(size_t)m * Nn + n] = vals[j];
            } else {
                C[(size_t)(m & 3) * ((size_t)Nn * AD) + (size_t)n * AD + (m >> 2)] = vals[j];
            }
        }
    }
}

// ---------------- flash attention v3 ----------------
// 2 threads per query (head-dim split 32+32), 128 threads = 64 queries per block.
// grid: (AN/64, AH) = 512 blocks -> single wave at 4 blocks/SM across 148 SMs.
// No online max (scores provably tiny for this model scale); exp2-domain softmax.
__global__ __launch_bounds__(128, 4) void attn_k(const float* __restrict__ Qp,
                                                 const float* __restrict__ Kp,
                                                 const float* __restrict__ Vp,
                                                 float* __restrict__ Msg) {
    __shared__ __align__(16) float4 ksh[2][32 * 16];   // 32 keys x 64 dims, double-buffered
    __shared__ __align__(16) float4 vsh[2][32 * 16];
    int h = blockIdx.y;
    int tid = threadIdx.x;
    int qi = (blockIdx.x << 6) + (tid >> 1);   // query index
    int half = tid & 1;                        // which 32 dims this thread owns

    const float* Kbase = Kp + (size_t)h * AN * AD;
    const float* Vbase = Vp + (size_t)h * AN * AD;

    // q half-row packed, pre-scaled by 1/8 * log2(e)
    ull q2[16];
    {
        const float4* qrow = (const float4*)(Qp + ((size_t)h * AN + qi) * AD + half * 32);
        const float qs = 0.125f * 1.4426950408889634f;
#pragma unroll
        for (int i = 0; i < 8; i++) {
            float4 t = qrow[i];
            q2[2 * i + 0] = pack2(t.x * qs, t.y * qs);
            q2[2 * i + 1] = pack2(t.z * qs, t.w * qs);
        }
    }
    ull O2[16];
#pragma unroll
    for (int i = 0; i < 16; i++) O2[i] = 0ull;
    float l = 0.f;

    unsigned kd0 = smem_u32(&ksh[0][0]);
    unsigned vd0 = smem_u32(&vsh[0][0]);
    const unsigned BUFB = 32 * 16 * 16;  // bytes per buffer

    // prologue: stage 0 (512 float4 per tensor, 128 threads -> 4 each)
    {
        const float4* Ks = (const float4*)Kbase;
        const float4* Vs = (const float4*)Vbase;
#pragma unroll
        for (int r = 0; r < 4; r++) {
            CPASYNC16(kd0 + (tid + 128 * r) * 16u, Ks + tid + 128 * r);
            CPASYNC16(vd0 + (tid + 128 * r) * 16u, Vs + tid + 128 * r);
        }
        CPASYNC_COMMIT();
        CPASYNC_WAIT0();
    }
    __syncthreads();

    const int nBlk = AN / 32;
    for (int it = 0; it < nBlk; it++) {
        int cur = it & 1;
        bool has_next = (it + 1 < nBlk);
        if (has_next) {
            int m0 = (it + 1) * 32;
            const float4* Ks = (const float4*)(Kbase + (size_t)m0 * AD);
            const float4* Vs = (const float4*)(Vbase + (size_t)m0 * AD);
            unsigned kd = kd0 + (cur ^ 1) * BUFB;
            unsigned vd = vd0 + (cur ^ 1) * BUFB;
#pragma unroll
            for (int r = 0; r < 4; r++) {
                CPASYNC16(kd + (tid + 128 * r) * 16u, Ks + tid + 128 * r);
                CPASYNC16(vd + (tid + 128 * r) * 16u, Vs + tid + 128 * r);
            }
            CPASYNC_COMMIT();
        }

#pragma unroll
        for (int jb = 0; jb < 32; jb += 8) {
            // --- phase 1: 8 partial scores over this thread's 32 dims ---
            float sp[8];
#pragma unroll
            for (int j = 0; j < 8; j++) {
                const ulonglong2* kr =
                    (const ulonglong2*)&ksh[cur][(jb + j) * 16 + half * 8];
                ull a0 = 0ull, a1 = 0ull;
#pragma unroll
                for (int i = 0; i < 8; i++) {
                    ulonglong2 t = kr[i];
                    a0 = fma2(q2[2 * i + 0], t.x, a0);
                    a1 = fma2(q2[2 * i + 1], t.y, a1);
                }
                ull ss = add2(a0, a1);
                float x0, x1;
                unpack2(ss, x0, x1);
                sp[j] = x0 + x1;
            }
            // --- phase 2: combine halves (pair lanes), exp2, accumulate l ---
#pragma unroll
            for (int j = 0; j < 8; j++)
                sp[j] += __shfl_xor_sync(0xffffffffu, sp[j], 1);
#pragma unroll
            for (int j = 0; j < 8; j++) sp[j] = ex2(sp[j]);
            l += ((sp[0] + sp[1]) + (sp[2] + sp[3])) +
                 ((sp[4] + sp[5]) + (sp[6] + sp[7]));
            // --- phase 3: PV accumulate over this thread's 32 dims ---
#pragma unroll
            for (int j = 0; j < 8; j++) {
                ull pv = pack2(sp[j], sp[j]);
                const ulonglong2* vr =
                    (const ulonglong2*)&vsh[cur][(jb + j) * 16 + half * 8];
#pragma unroll
                for (int i = 0; i < 8; i++) {
                    ulonglong2 t = vr[i];
                    O2[2 * i + 0] = fma2(pv, t.x, O2[2 * i + 0]);
                    O2[2 * i + 1] = fma2(pv, t.y, O2[2 * i + 1]);
                }
            }
        }

        if (has_next) {
            CPASYNC_WAIT0();
            __syncthreads();
        }
    }

    float inv = 1.f / l;
    // dims d = half*32 + 2i(+1) ; Msg channel = d*4 + h ; Msg[(c)*AN + qi]
    float* base = Msg + (size_t)h * AN + qi;
#pragma unroll
    for (int i = 0; i < 16; i++) {
        float x0, x1;
        unpack2(O2[i], x0, x1);
        int d0 = half * 32 + 2 * i;
        base[(size_t)(4 * d0) * AN] = x0 * inv;
        base[(size_t)(4 * (d0 + 1)) * AN] = x1 * inv;
    }
}

// ---------------- InstanceNorm (biased var) + ReLU, in place, per channel ----------------
__global__ __launch_bounds__(256) void inorm_relu(float* __restrict__ Y) {
    const int Nn = AN;
    float* row = Y + (size_t)blockIdx.x * Nn;
    __shared__ float red[256];
    int tid = threadIdx.x;

    float s = 0.f;
    for (int i = tid; i < Nn; i += 256) s += row[i];
    red[tid] = s;
    __syncthreads();
    for (int off = 128; off > 0; off >>= 1) {
        if (tid < off) red[tid] += red[tid + off];
        __syncthreads();
    }
    float mean = red[0] * (1.f / Nn);
    __syncthreads();

    float ss = 0.f;
    for (int i = tid; i < Nn; i += 256) {
        float d = row[i] - mean;
        ss += d * d;
    }
    red[tid] = ss;
    __syncthreads();
    for (int off = 128; off > 0; off >>= 1) {
        if (tid < off) red[tid] += red[tid + off];
        __syncthreads();
    }
    float rstd = rsqrtf(red[0] * (1.f / Nn) + 1e-5f);

    for (int i = tid; i < Nn; i += 256) {
        float v = (row[i] - mean) * rstd;
        row[i] = v > 0.f ? v : 0.f;
    }
}

// ---------------- launch ----------------
extern "C" void kernel_launch(void* const* d_in, const int* in_sizes, int n_in,
                              void* d_out, int out_size) {
    const float* descs = (const float*)d_in[0];
    const float* Wq = (const float*)d_in[1];
    const float* bq = (const float*)d_in[2];
    const float* Wk = (const float*)d_in[3];
    const float* bk = (const float*)d_in[4];
    const float* Wv = (const float*)d_in[5];
    const float* bv = (const float*)d_in[6];
    const float* Wm = (const float*)d_in[7];
    const float* bm = (const float*)d_in[8];
    const float* W1 = (const float*)d_in[9];
    const float* b1 = (const float*)d_in[10];
    const float* W2 = (const float*)d_in[11];
    const float* b2 = (const float*)d_in[12];
    float* out = (float*)d_out;

    float *xm, *q, *k, *v, *msg, *y, *z;
    cudaGetSymbolAddress((void**)&xm, g_XM);
    cudaGetSymbolAddress((void**)&q, g_Q);
    cudaGetSymbolAddress((void**)&k, g_K);
    cudaGetSymbolAddress((void**)&v, g_V);
    cudaGetSymbolAddress((void**)&msg, g_Msg);
    cudaGetSymbolAddress((void**)&y, g_Y);
    cudaGetSymbolAddress((void**)&z, g_Z);

    dim3 tb(32, 8);

    transpose_in<<<dim3(AN / 32, AC / 32), tb>>>(descs, xm);

    gemm_k<1><<<dim3(AN / 64, AC / 64), 256>>>(Wq, xm, bq, q, AC, AN, AC);
    gemm_k<1><<<dim3(AN / 64, AC / 64), 256>>>(Wk, xm, bk, k, AC, AN, AC);
    gemm_k<1><<<dim3(AN / 64, AC / 64), 256>>>(Wv, xm, bv, v, AC, AN, AC);

    attn_k<<<dim3(AN / 64, AH), 128>>>(q, k, v, msg);

    gemm_k<0><<<dim3(AN / 64, AC / 64), 256>>>(Wm, msg, bm, xm + (size_t)AC * AN, AC, AN, AC);

    gemm_k<0><<<dim3(AN / 64, AC2 / 64), 256>>>(W1, xm, b1, y, AC2, AN, AC2);

    inorm_relu<<<AC2, 256>>>(y);

    gemm_k<0><<<dim3(AN / 64, AC / 64), 256>>>(W2, y, b2, z, AC, AN, AC2);

    transpose_add<<<dim3(AN / 32, AC / 32), tb>>>(descs, z, out);
}

// round 5
// speedup vs baseline: 7.6927x; 7.6927x over previous
#include <cuda_runtime.h>
#include <cuda_bf16.h>
#include <cstddef>

#define AN 8192          // sequence length
#define AC 256           // channels
#define AH 4             // heads
#define AD 64            // head dim
#define AC2 512          // 2*C
#define LG2E_D8 0.1803368801111601f   // log2(e)/8

typedef unsigned long long ull;
typedef unsigned int u32;

// ---------------- packed f32x2 helpers ----------------
__device__ __forceinline__ ull fma2(ull a, ull b, ull c) {
    ull d;
    asm("fma.rn.f32x2 %0, %1, %2, %3;" : "=l"(d) : "l"(a), "l"(b), "l"(c));
    return d;
}
__device__ __forceinline__ ull pack2(float x, float y) {
    ull r;
    asm("mov.b64 %0, {%1, %2};" : "=l"(r) : "f"(x), "f"(y));
    return r;
}
__device__ __forceinline__ void unpack2(ull v, float& x, float& y) {
    asm("mov.b64 {%0, %1}, %2;" : "=f"(x), "=f"(y) : "l"(v));
}
__device__ __forceinline__ float ex2(float x) {
    float y;
    asm("ex2.approx.f32 %0, %1;" : "=f"(y) : "f"(x));
    return y;
}
__device__ __forceinline__ u32 smem_u32(const void* p) {
    u32 r;
    asm("{.reg .u64 t; cvta.to.shared.u64 t, %1; cvt.u32.u64 %0, t;}" : "=r"(r) : "l"(p));
    return r;
}
#define CPASYNC16(dst, src) \
    asm volatile("cp.async.cg.shared.global [%0], [%1], 16;" :: "r"(dst), "l"(src))
#define CPASYNC_COMMIT() asm volatile("cp.async.commit_group;" ::: "memory")

// ---------------- mma / ldmatrix helpers ----------------
__device__ __forceinline__ void ldsm_x4(u32 a, u32& r0, u32& r1, u32& r2, u32& r3) {
    asm volatile("ldmatrix.sync.aligned.m8n8.x4.shared.b16 {%0,%1,%2,%3}, [%4];"
                 : "=r"(r0), "=r"(r1), "=r"(r2), "=r"(r3) : "r"(a));
}
__device__ __forceinline__ void ldsm_x2(u32 a, u32& r0, u32& r1) {
    asm volatile("ldmatrix.sync.aligned.m8n8.x2.shared.b16 {%0,%1}, [%2];"
                 : "=r"(r0), "=r"(r1) : "r"(a));
}
__device__ __forceinline__ void ldsm_x2t(u32 a, u32& r0, u32& r1) {
    asm volatile("ldmatrix.sync.aligned.m8n8.x2.trans.shared.b16 {%0,%1}, [%2];"
                 : "=r"(r0), "=r"(r1) : "r"(a));
}
__device__ __forceinline__ void mma_bf16(float* c, const u32* a, u32 b0, u32 b1) {
    asm volatile(
        "mma.sync.aligned.m16n8k16.row.col.f32.bf16.bf16.f32 "
        "{%0,%1,%2,%3}, {%4,%5,%6,%7}, {%8,%9}, {%0,%1,%2,%3};"
        : "+f"(c[0]), "+f"(c[1]), "+f"(c[2]), "+f"(c[3])
        : "r"(a[0]), "r"(a[1]), "r"(a[2]), "r"(a[3]), "r"(b0), "r"(b1));
}
__device__ __forceinline__ u32 cvtbf2(float hi, float lo) {
    u32 d;
    asm("cvt.rn.bf16x2.f32 %0, %1, %2;" : "=r"(d) : "f"(hi), "f"(lo));
    return d;
}

// ---------------- scratch (allocation-free, device globals) ----------------
__device__ float g_XM[(size_t)AC2 * AN];
__device__ __nv_bfloat16 g_Qb[(size_t)AH * AN * AD];   // [h][n][d], pre-scaled by log2e/8
__device__ __nv_bfloat16 g_Kb[(size_t)AH * AN * AD];
__device__ __nv_bfloat16 g_Vb[(size_t)AH * AN * AD];
__device__ float g_Msg[(size_t)AC * AN];
__device__ float g_Y[(size_t)AC2 * AN];
__device__ float g_Z[(size_t)AC * AN];

// ---------------- transpose: X[c][n] = descs[n][c] ----------------
__global__ __launch_bounds__(256) void transpose_in(const float* __restrict__ descs,
                                                    float* __restrict__ X) {
    __shared__ float tile[32][33];
    int n0 = blockIdx.x * 32, c0 = blockIdx.y * 32;
    int tx = threadIdx.x, ty = threadIdx.y;
#pragma unroll
    for (int r = 0; r < 4; r++) {
        int n = n0 + ty + r * 8;
        tile[ty + r * 8][tx] = descs[(size_t)n * AC + c0 + tx];
    }
    __syncthreads();
#pragma unroll
    for (int r = 0; r < 4; r++) {
        int c = c0 + ty + r * 8;
        X[(size_t)c * AN + n0 + tx] = tile[tx][ty + r * 8];
    }
}

// ---------------- out[n][c] = descs[n][c] + Z[c][n] ----------------
__global__ __launch_bounds__(256) void transpose_add(const float* __restrict__ descs,
                                                     const float* __restrict__ Z,
                                                     float* __restrict__ out) {
    __shared__ float tile[32][33];
    int n0 = blockIdx.x * 32, c0 = blockIdx.y * 32;
    int tx = threadIdx.x, ty = threadIdx.y;
#pragma unroll
    for (int r = 0; r < 4; r++) {
        int c = c0 + ty + r * 8;
        tile[ty + r * 8][tx] = Z[(size_t)c * AN + n0 + tx];
    }
    __syncthreads();
#pragma unroll
    for (int r = 0; r < 4; r++) {
        int n = n0 + ty + r * 8;
        size_t idx = (size_t)n * AC + c0 + tx;
        out[idx] = descs[idx] + tile[tx][ty + r * 8];
    }
}

// ---------------- fp32 GEMM: C = A[M,K] @ B[K,N] + bias ----------------
// OUTMODE 0: fp32 C[m][n]. OUTMODE 1: bf16 QKV permute [h][n][d].
// OUTMODE 2: like 1 but scaled by log2e/8 (for Q).
template <int OUTMODE>
__global__ __launch_bounds__(256) void gemm_k(const float* __restrict__ A,
                                              const float* __restrict__ B,
                                              const float* __restrict__ bias,
                                              float* __restrict__ C,
                                              int M, int Nn, int K) {
    __shared__ __align__(16) float As[2][16][64];
    __shared__ __align__(16) float Bs[2][16][64];
    int tid = threadIdx.x;
    int n0 = blockIdx.x * 64;
    int m0 = blockIdx.y * 64;
    int tx = tid & 15, ty = tid >> 4;
    int ar = tid >> 2, ac4 = tid & 3;
    int br = tid >> 4, bc4 = tid & 15;

    ull acc2[4][2];
#pragma unroll
    for (int i = 0; i < 4; i++) { acc2[i][0] = 0ull; acc2[i][1] = 0ull; }

    {
        float4 a = *(const float4*)&A[(size_t)(m0 + ar) * K + ac4 * 4];
        float4 b = *(const float4*)&B[(size_t)br * Nn + n0 + bc4 * 4];
        As[0][ac4 * 4 + 0][ar] = a.x;
        As[0][ac4 * 4 + 1][ar] = a.y;
        As[0][ac4 * 4 + 2][ar] = a.z;
        As[0][ac4 * 4 + 3][ar] = a.w;
        *(float4*)&Bs[0][br][bc4 * 4] = b;
    }
    __syncthreads();

    int nIter = K >> 4;
    for (int it = 0; it < nIter; it++) {
        int cur = it & 1;
        float4 an, bn;
        bool has_next = (it + 1 < nIter);
        if (has_next) {
            int k0 = (it + 1) << 4;
            an = *(const float4*)&A[(size_t)(m0 + ar) * K + k0 + ac4 * 4];
            bn = *(const float4*)&B[(size_t)(k0 + br) * Nn + n0 + bc4 * 4];
        }
#pragma unroll
        for (int kk = 0; kk < 16; kk++) {
            float4 av = *(const float4*)&As[cur][kk][ty * 4];
            ulonglong2 bb = *(const ulonglong2*)&Bs[cur][kk][tx * 4];
            ull a0 = pack2(av.x, av.x);
            ull a1 = pack2(av.y, av.y);
            ull a2 = pack2(av.z, av.z);
            ull a3 = pack2(av.w, av.w);
            acc2[0][0] = fma2(a0, bb.x, acc2[0][0]);
            acc2[0][1] = fma2(a0, bb.y, acc2[0][1]);
            acc2[1][0] = fma2(a1, bb.x, acc2[1][0]);
            acc2[1][1] = fma2(a1, bb.y, acc2[1][1]);
            acc2[2][0] = fma2(a2, bb.x, acc2[2][0]);
            acc2[2][1] = fma2(a2, bb.y, acc2[2][1]);
            acc2[3][0] = fma2(a3, bb.x, acc2[3][0]);
            acc2[3][1] = fma2(a3, bb.y, acc2[3][1]);
        }
        if (has_next) {
            int nxt = cur ^ 1;
            As[nxt][ac4 * 4 + 0][ar] = an.x;
            As[nxt][ac4 * 4 + 1][ar] = an.y;
            As[nxt][ac4 * 4 + 2][ar] = an.z;
            As[nxt][ac4 * 4 + 3][ar] = an.w;
            *(float4*)&Bs[nxt][br][bc4 * 4] = bn;
            __syncthreads();
        }
    }

#pragma unroll
    for (int i = 0; i < 4; i++) {
        int m = m0 + ty * 4 + i;
        float bv = bias[m];
        float c0, c1, c2, c3;
        unpack2(acc2[i][0], c0, c1);
        unpack2(acc2[i][1], c2, c3);
        float vals[4] = {c0 + bv, c1 + bv, c2 + bv, c3 + bv};
#pragma unroll
        for (int j = 0; j < 4; j++) {
            int n = n0 + tx * 4 + j;
            if (OUTMODE == 0) {
                C[(size_t)m * Nn + n] = vals[j];
            } else {
                __nv_bfloat16* Cb = reinterpret_cast<__nv_bfloat16*>(C);
                float sv = (OUTMODE == 2) ? vals[j] * LG2E_D8 : vals[j];
                Cb[(size_t)(m & 3) * ((size_t)Nn * AD) + (size_t)n * AD + (m >> 2)] =
                    __float2bfloat16(sv);
            }
        }
    }
}

// ---------------- tensor-core flash attention ----------------
// 4 warps, 64 queries/block (16 per warp), 64-key tiles, bf16 mma, no online max.
// grid: (AN/64, AH) = 512 blocks.
#define KSTRIDE 72          // bf16 elements per smem row (64 + 8 pad)
#define KSTRIDE_B 144       // bytes
#define TILE_E (64 * KSTRIDE)

__global__ __launch_bounds__(128, 4) void attn_k(const __nv_bfloat16* __restrict__ Qp,
                                                 const __nv_bfloat16* __restrict__ Kp,
                                                 const __nv_bfloat16* __restrict__ Vp,
                                                 float* __restrict__ Msg) {
    __shared__ __align__(16) __nv_bfloat16 Qs[TILE_E];
    __shared__ __align__(16) __nv_bfloat16 Ks[2][TILE_E];
    __shared__ __align__(16) __nv_bfloat16 Vs[2][TILE_E];

    const int tid = threadIdx.x;
    const int lane = tid & 31, warp = tid >> 5;
    const int h = blockIdx.y;
    const int n0 = blockIdx.x * 64;
    const int m0w = warp * 16;

    const __nv_bfloat16* Qg = Qp + ((size_t)h * AN + n0) * AD;
    const __nv_bfloat16* Kg = Kp + (size_t)h * AN * AD;
    const __nv_bfloat16* Vg = Vp + (size_t)h * AN * AD;

    u32 qb = smem_u32(Qs);
    u32 kb0 = smem_u32(Ks);
    u32 vb0 = smem_u32(Vs);

    // loader mapping: chunk c -> row=c>>3, 16B-col=c&7
    int lrow[4], lcol[4];
#pragma unroll
    for (int r = 0; r < 4; r++) {
        int c = tid + 128 * r;
        lrow[r] = c >> 3;
        lcol[r] = c & 7;
    }

    // prologue: stage Q + K0 + V0 (group0), K1 + V1 (group1)
#pragma unroll
    for (int r = 0; r < 4; r++) {
        u32 so = lrow[r] * KSTRIDE_B + lcol[r] * 16;
        size_t go = (size_t)lrow[r] * AD + lcol[r] * 8;
        CPASYNC16(qb + so, Qg + go);
        CPASYNC16(kb0 + so, Kg + go);
        CPASYNC16(vb0 + so, Vg + go);
    }
    CPASYNC_COMMIT();
#pragma unroll
    for (int r = 0; r < 4; r++) {
        u32 so = TILE_E * 2 + lrow[r] * KSTRIDE_B + lcol[r] * 16;  // buffer 1 (bytes)
        size_t go = (size_t)(64 + lrow[r]) * AD + lcol[r] * 8;
        CPASYNC16(kb0 + so, Kg + go);
        CPASYNC16(vb0 + so, Vg + go);
    }
    CPASYNC_COMMIT();
    asm volatile("cp.async.wait_group 1;" ::: "memory");
    __syncthreads();

    // Q a-fragments (4 k-steps of 16)
    u32 qa[4][4];
    {
        u32 qaddr = qb + (m0w + (lane & 15)) * KSTRIDE_B + (lane >> 4) * 16;
#pragma unroll
        for (int kk = 0; kk < 4; kk++)
            ldsm_x4(qaddr + kk * 32, qa[kk][0], qa[kk][1], qa[kk][2], qa[kk][3]);
    }

    float O[8][4];
#pragma unroll
    for (int t = 0; t < 8; t++) { O[t][0] = O[t][1] = O[t][2] = O[t][3] = 0.f; }
    float rs0 = 0.f, rs1 = 0.f;

    // per-lane ldmatrix base offsets (within a tile)
    const u32 kfb = (lane & 7) * KSTRIDE_B + ((lane >> 3) & 1) * 16;   // + t*8*stride + kk*32
    const u32 vfb = ((lane & 7) + ((lane >> 3) & 1) * 8) * KSTRIDE_B; // + kk2*16*stride + t*16

    const int nIter = AN / 64;
    for (int it = 0; it < nIter; it++) {
        u32 kb = kb0 + (u32)(it & 1) * (TILE_E * 2);
        u32 vb = vb0 + (u32)(it & 1) * (TILE_E * 2);

        // ---- scores S = Q @ K^T (exp2-domain: Q pre-scaled) ----
        float S[8][4];
#pragma unroll
        for (int t = 0; t < 8; t++) { S[t][0] = S[t][1] = S[t][2] = S[t][3] = 0.f; }
#pragma unroll
        for (int kk = 0; kk < 4; kk++) {
#pragma unroll
            for (int t = 0; t < 8; t++) {
                u32 b0, b1;
                ldsm_x2(kb + kfb + t * (8 * KSTRIDE_B) + kk * 32, b0, b1);
                mma_bf16(S[t], qa[kk], b0, b1);
            }
        }
        // ---- softmax (no max) + convert P to A-frags ----
        u32 pa[4][4];
#pragma unroll
        for (int t = 0; t < 8; t += 2) {
#pragma unroll
            for (int e = 0; e < 4; e++) {
                S[t][e] = ex2(S[t][e]);
                S[t + 1][e] = ex2(S[t + 1][e]);
            }
            rs0 += (S[t][0] + S[t][1]) + (S[t + 1][0] + S[t + 1][1]);
            rs1 += (S[t][2] + S[t][3]) + (S[t + 1][2] + S[t + 1][3]);
            int kk2 = t >> 1;
            pa[kk2][0] = cvtbf2(S[t][1], S[t][0]);
            pa[kk2][1] = cvtbf2(S[t][3], S[t][2]);
            pa[kk2][2] = cvtbf2(S[t + 1][1], S[t + 1][0]);
            pa[kk2][3] = cvtbf2(S[t + 1][3], S[t + 1][2]);
        }
        // ---- O += P @ V ----
#pragma unroll
        for (int kk2 = 0; kk2 < 4; kk2++) {
#pragma unroll
            for (int t = 0; t < 8; t++) {
                u32 b0, b1;
                ldsm_x2t(vb + vfb + kk2 * (16 * KSTRIDE_B) + t * 16, b0, b1);
                mma_bf16(O[t], pa[kk2], b0, b1);
            }
        }

        __syncthreads();   // all warps done reading buffer (it&1)
        if (it + 2 < nIter) {
            int m0 = (it + 2) * 64;
            u32 kbn = kb0 + (u32)(it & 1) * (TILE_E * 2);
            u32 vbn = vb0 + (u32)(it & 1) * (TILE_E * 2);
#pragma unroll
            for (int r = 0; r < 4; r++) {
                u32 so = lrow[r] * KSTRIDE_B + lcol[r] * 16;
                size_t go = (size_t)(m0 + lrow[r]) * AD + lcol[r] * 8;
                CPASYNC16(kbn + so, Kg + go);
                CPASYNC16(vbn + so, Vg + go);
            }
            CPASYNC_COMMIT();
        }
        asm volatile("cp.async.wait_group 1;" ::: "memory");
        __syncthreads();   // next buffer visible to all
    }

    // row-sum reduce across the quad
    rs0 += __shfl_xor_sync(0xffffffffu, rs0, 1);
    rs0 += __shfl_xor_sync(0xffffffffu, rs0, 2);
    rs1 += __shfl_xor_sync(0xffffffffu, rs1, 1);
    rs1 += __shfl_xor_sync(0xffffffffu, rs1, 2);
    float inv0 = 1.f / rs0, inv1 = 1.f / rs1;

    int r0 = n0 + m0w + (lane >> 2);
    int r1 = r0 + 8;
    float* mbase = Msg + (size_t)h * AN;
#pragma unroll
    for (int t = 0; t < 8; t++) {
        int d0 = t * 8 + (lane & 3) * 2;
        mbase[(size_t)(4 * d0) * AN + r0] = O[t][0] * inv0;
        mbase[(size_t)(4 * (d0 + 1)) * AN + r0] = O[t][1] * inv0;
        mbase[(size_t)(4 * d0) * AN + r1] = O[t][2] * inv1;
        mbase[(size_t)(4 * (d0 + 1)) * AN + r1] = O[t][3] * inv1;
    }
}

// ---------------- InstanceNorm (biased var) + ReLU ----------------
__global__ __launch_bounds__(256) void inorm_relu(float* __restrict__ Y) {
    const int Nn = AN;
    float* row = Y + (size_t)blockIdx.x * Nn;
    __shared__ float red[256];
    int tid = threadIdx.x;

    float s = 0.f;
    for (int i = tid; i < Nn; i += 256) s += row[i];
    red[tid] = s;
    __syncthreads();
    for (int off = 128; off > 0; off >>= 1) {
        if (tid < off) red[tid] += red[tid + off];
        __syncthreads();
    }
    float mean = red[0] * (1.f / Nn);
    __syncthreads();

    float ss = 0.f;
    for (int i = tid; i < Nn; i += 256) {
        float d = row[i] - mean;
        ss += d * d;
    }
    red[tid] = ss;
    __syncthreads();
    for (int off = 128; off > 0; off >>= 1) {
        if (tid < off) red[tid] += red[tid + off];
        __syncthreads();
    }
    float rstd = rsqrtf(red[0] * (1.f / Nn) + 1e-5f);

    for (int i = tid; i < Nn; i += 256) {
        float v = (row[i] - mean) * rstd;
        row[i] = v > 0.f ? v : 0.f;
    }
}

// ---------------- launch ----------------
extern "C" void kernel_launch(void* const* d_in, const int* in_sizes, int n_in,
                              void* d_out, int out_size) {
    const float* descs = (const float*)d_in[0];
    const float* Wq = (const float*)d_in[1];
    const float* bq = (const float*)d_in[2];
    const float* Wk = (const float*)d_in[3];
    const float* bk = (const float*)d_in[4];
    const float* Wv = (const float*)d_in[5];
    const float* bv = (const float*)d_in[6];
    const float* Wm = (const float*)d_in[7];
    const float* bm = (const float*)d_in[8];
    const float* W1 = (const float*)d_in[9];
    const float* b1 = (const float*)d_in[10];
    const float* W2 = (const float*)d_in[11];
    const float* b2 = (const float*)d_in[12];
    float* out = (float*)d_out;

    float *xm, *msg, *y, *z;
    __nv_bfloat16 *qb, *kb, *vb;
    cudaGetSymbolAddress((void**)&xm, g_XM);
    cudaGetSymbolAddress((void**)&qb, g_Qb);
    cudaGetSymbolAddress((void**)&kb, g_Kb);
    cudaGetSymbolAddress((void**)&vb, g_Vb);
    cudaGetSymbolAddress((void**)&msg, g_Msg);
    cudaGetSymbolAddress((void**)&y, g_Y);
    cudaGetSymbolAddress((void**)&z, g_Z);

    dim3 tb(32, 8);

    transpose_in<<<dim3(AN / 32, AC / 32), tb>>>(descs, xm);

    gemm_k<2><<<dim3(AN / 64, AC / 64), 256>>>(Wq, xm, bq, (float*)qb, AC, AN, AC);
    gemm_k<1><<<dim3(AN / 64, AC / 64), 256>>>(Wk, xm, bk, (float*)kb, AC, AN, AC);
    gemm_k<1><<<dim3(AN / 64, AC / 64), 256>>>(Wv, xm, bv, (float*)vb, AC, AN, AC);

    attn_k<<<dim3(AN / 64, AH), 128>>>(qb, kb, vb, msg);

    gemm_k<0><<<dim3(AN / 64, AC / 64), 256>>>(Wm, msg, bm, xm + (size_t)AC * AN, AC, AN, AC);

    gemm_k<0><<<dim3(AN / 64, AC2 / 64), 256>>>(W1, xm, b1, y, AC2, AN, AC2);

    inorm_relu<<<AC2, 256>>>(y);

    gemm_k<0><<<dim3(AN / 64, AC / 64), 256>>>(W2, y, b2, z, AC, AN, AC2);

    transpose_add<<<dim3(AN / 32, AC / 32), tb>>>(descs, z, out);
}

// round 6
// speedup vs baseline: 11.3807x; 1.4794x over previous
#include <cuda_runtime.h>
#include <cuda_bf16.h>
#include <cstddef>

#define AN 8192          // sequence length
#define AC 256           // channels
#define AH 4             // heads
#define AD 64            // head dim
#define AC2 512          // 2*C
#define LG2E_D8 0.1803368801111601f   // log2(e)/8

typedef unsigned long long ull;
typedef unsigned int u32;

// ---------------- helpers ----------------
__device__ __forceinline__ float ex2(float x) {
    float y;
    asm("ex2.approx.f32 %0, %1;" : "=f"(y) : "f"(x));
    return y;
}
__device__ __forceinline__ float rna_tf32(float x) {
    u32 y;
    asm("cvt.rna.tf32.f32 %0, %1;" : "=r"(y) : "f"(x));
    return __uint_as_float(y);
}
__device__ __forceinline__ u32 smem_u32(const void* p) {
    u32 r;
    asm("{.reg .u64 t; cvta.to.shared.u64 t, %1; cvt.u32.u64 %0, t;}" : "=r"(r) : "l"(p));
    return r;
}
#define CPASYNC16(dst, src) \
    asm volatile("cp.async.cg.shared.global [%0], [%1], 16;" :: "r"(dst), "l"(src))
#define CPASYNC_COMMIT() asm volatile("cp.async.commit_group;" ::: "memory")

// ---------------- mma / ldmatrix ----------------
__device__ __forceinline__ void ldsm_x4(u32 a, u32& r0, u32& r1, u32& r2, u32& r3) {
    asm volatile("ldmatrix.sync.aligned.m8n8.x4.shared.b16 {%0,%1,%2,%3}, [%4];"
                 : "=r"(r0), "=r"(r1), "=r"(r2), "=r"(r3) : "r"(a));
}
__device__ __forceinline__ void ldsm_x2(u32 a, u32& r0, u32& r1) {
    asm volatile("ldmatrix.sync.aligned.m8n8.x2.shared.b16 {%0,%1}, [%2];"
                 : "=r"(r0), "=r"(r1) : "r"(a));
}
__device__ __forceinline__ void ldsm_x2t(u32 a, u32& r0, u32& r1) {
    asm volatile("ldmatrix.sync.aligned.m8n8.x2.trans.shared.b16 {%0,%1}, [%2];"
                 : "=r"(r0), "=r"(r1) : "r"(a));
}
__device__ __forceinline__ void mma_bf16(float* c, const u32* a, u32 b0, u32 b1) {
    asm volatile(
        "mma.sync.aligned.m16n8k16.row.col.f32.bf16.bf16.f32 "
        "{%0,%1,%2,%3}, {%4,%5,%6,%7}, {%8,%9}, {%0,%1,%2,%3};"
        : "+f"(c[0]), "+f"(c[1]), "+f"(c[2]), "+f"(c[3])
        : "r"(a[0]), "r"(a[1]), "r"(a[2]), "r"(a[3]), "r"(b0), "r"(b1));
}
__device__ __forceinline__ void mma_tf32(float* c, const u32* a, u32 b0, u32 b1) {
    asm volatile(
        "mma.sync.aligned.m16n8k8.row.col.f32.tf32.tf32.f32 "
        "{%0,%1,%2,%3}, {%4,%5,%6,%7}, {%8,%9}, {%0,%1,%2,%3};"
        : "+f"(c[0]), "+f"(c[1]), "+f"(c[2]), "+f"(c[3])
        : "r"(a[0]), "r"(a[1]), "r"(a[2]), "r"(a[3]), "r"(b0), "r"(b1));
}
__device__ __forceinline__ u32 cvtbf2(float hi, float lo) {
    u32 d;
    asm("cvt.rn.bf16x2.f32 %0, %1, %2;" : "=r"(d) : "f"(hi), "f"(lo));
    return d;
}

// ---------------- scratch (allocation-free, device globals) ----------------
__device__ float g_XM[(size_t)AC2 * AN];               // rows 0..255: X ; 256..511: Wm@msg
__device__ __nv_bfloat16 g_Qb[(size_t)AH * AN * AD];
__device__ __nv_bfloat16 g_Kb[(size_t)AH * AN * AD];
__device__ __nv_bfloat16 g_Vb[(size_t)AH * AN * AD];
__device__ float g_Msg[(size_t)AC * AN];
__device__ float g_Y[(size_t)AC2 * AN];
__device__ float g_Z[(size_t)AC * AN];
// prerounded tf32 weights: Wq | Wk | Wv | Wm | W1 | W2
#define WOFF_Q 0
#define WOFF_K 65536
#define WOFF_V 131072
#define WOFF_M 196608
#define WOFF_1 262144
#define WOFF_2 524288
#define WTOT   655360
__device__ float g_Wbuf[WTOT];

// ---------------- weight preround to tf32 (rna) ----------------
__global__ __launch_bounds__(256) void preround_w(const float* __restrict__ wq,
                                                  const float* __restrict__ wk,
                                                  const float* __restrict__ wv,
                                                  const float* __restrict__ wm,
                                                  const float* __restrict__ w1,
                                                  const float* __restrict__ w2,
                                                  float* __restrict__ dst) {
    for (int i = blockIdx.x * 256 + threadIdx.x; i < WTOT; i += gridDim.x * 256) {
        float v;
        if (i < WOFF_K) v = wq[i];
        else if (i < WOFF_V) v = wk[i - WOFF_K];
        else if (i < WOFF_M) v = wv[i - WOFF_V];
        else if (i < WOFF_1) v = wm[i - WOFF_M];
        else if (i < WOFF_2) v = w1[i - WOFF_1];
        else v = w2[i - WOFF_2];
        dst[i] = rna_tf32(v);
    }
}

// ---------------- transpose: X[c][n] = rna(descs[n][c]) ----------------
__global__ __launch_bounds__(256) void transpose_in(const float* __restrict__ descs,
                                                    float* __restrict__ X) {
    __shared__ float tile[32][33];
    int n0 = blockIdx.x * 32, c0 = blockIdx.y * 32;
    int tx = threadIdx.x, ty = threadIdx.y;
#pragma unroll
    for (int r = 0; r < 4; r++) {
        int n = n0 + ty + r * 8;
        tile[ty + r * 8][tx] = descs[(size_t)n * AC + c0 + tx];
    }
    __syncthreads();
#pragma unroll
    for (int r = 0; r < 4; r++) {
        int c = c0 + ty + r * 8;
        X[(size_t)c * AN + n0 + tx] = rna_tf32(tile[tx][ty + r * 8]);
    }
}

// ---------------- out[n][c] = descs[n][c] + Z[c][n] ----------------
__global__ __launch_bounds__(256) void transpose_add(const float* __restrict__ descs,
                                                     const float* __restrict__ Z,
                                                     float* __restrict__ out) {
    __shared__ float tile[32][33];
    int n0 = blockIdx.x * 32, c0 = blockIdx.y * 32;
    int tx = threadIdx.x, ty = threadIdx.y;
#pragma unroll
    for (int r = 0; r < 4; r++) {
        int c = c0 + ty + r * 8;
        tile[ty + r * 8][tx] = Z[(size_t)c * AN + n0 + tx];
    }
    __syncthreads();
#pragma unroll
    for (int r = 0; r < 4; r++) {
        int n = n0 + ty + r * 8;
        size_t idx = (size_t)n * AC + c0 + tx;
        out[idx] = descs[idx] + tile[tx][ty + r * 8];
    }
}

// ================= tf32 tensor-core GEMM =================
// block tile 128x128, BK=16, 128 threads (4 warps, each 64x64).
// As[m][k] stride 20 (pad), Bs[k][n] stride 128 with XOR-8 swizzle on n by (k&3).
#define GA_STRIDE 20
#define GA_BUF (128 * GA_STRIDE)
#define GB_BUF (16 * 128)

struct GemmFrag {
    float acc[4][8][4];
};

__device__ __forceinline__ void gemm_load_stage(const float* __restrict__ A,
                                                const float* __restrict__ B,
                                                int Nn, int K, int m0, int n0,
                                                int tid, int s, int k0,
                                                u32 asb, u32 bsb) {
    u32 ad = asb + (u32)s * (GA_BUF * 4) + (u32)(tid * GA_STRIDE) * 4;
    const float* ag = A + (size_t)(m0 + tid) * K + k0;
#pragma unroll
    for (int j = 0; j < 4; j++) CPASYNC16(ad + j * 16, ag + j * 4);
    int kr = tid >> 3;
    int cb = (tid & 7) * 16;
    u32 bd = bsb + (u32)s * (GB_BUF * 4) + (u32)(kr * 128) * 4;
    const float* bg = B + (size_t)(k0 + kr) * Nn + n0 + cb;
#pragma unroll
    for (int j = 0; j < 4; j++) {
        int pc = (cb + 4 * j) ^ ((kr & 3) << 3);
        CPASYNC16(bd + (u32)pc * 4, bg + 4 * j);
    }
}

__device__ __forceinline__ void gemm_mainloop(const float* __restrict__ A,
                                              const float* __restrict__ B,
                                              int Nn, int K, int m0, int n0,
                                              int tid, int lane, int wm, int wn,
                                              const float* As, const float* Bs,
                                              u32 asb, u32 bsb, GemmFrag& F) {
#pragma unroll
    for (int mt = 0; mt < 4; mt++)
#pragma unroll
        for (int nt = 0; nt < 8; nt++)
#pragma unroll
            for (int e = 0; e < 4; e++) F.acc[mt][nt][e] = 0.f;

    gemm_load_stage(A, B, Nn, K, m0, n0, tid, 0, 0, asb, bsb);
    CPASYNC_COMMIT();

    const int nIter = K >> 4;
    for (int it = 0; it < nIter; it++) {
        if (it + 1 < nIter) {
            gemm_load_stage(A, B, Nn, K, m0, n0, tid, (it + 1) & 1, (it + 1) * 16, asb, bsb);
            CPASYNC_COMMIT();
            asm volatile("cp.async.wait_group 1;" ::: "memory");
        } else {
            asm volatile("cp.async.wait_group 0;" ::: "memory");
        }
        __syncthreads();
        const float* as = As + (it & 1) * GA_BUF;
        const float* bs = Bs + (it & 1) * GB_BUF;
#pragma unroll
        for (int kk = 0; kk < 2; kk++) {
            u32 af[4][4];
            const int c = kk * 8 + (lane & 3);
#pragma unroll
            for (int mt = 0; mt < 4; mt++) {
                int r = wm + mt * 16 + (lane >> 2);
                af[mt][0] = __float_as_uint(as[r * GA_STRIDE + c]);
                af[mt][1] = __float_as_uint(as[(r + 8) * GA_STRIDE + c]);
                af[mt][2] = __float_as_uint(as[r * GA_STRIDE + c + 4]);
                af[mt][3] = __float_as_uint(as[(r + 8) * GA_STRIDE + c + 4]);
            }
#pragma unroll
            for (int nt = 0; nt < 8; nt++) {
                int nb = (wn + nt * 8 + (lane >> 2)) ^ ((lane & 3) << 3);
                u32 b0 = __float_as_uint(bs[c * 128 + nb]);
                u32 b1 = __float_as_uint(bs[(c + 4) * 128 + nb]);
#pragma unroll
                for (int mt = 0; mt < 4; mt++) mma_tf32(F.acc[mt][nt], af[mt], b0, b1);
            }
        }
        __syncthreads();
    }
}

// OUTMODE 0: fp32 raw; 3: fp32 rounded to tf32 (feeds another mma)
template <int OUTMODE>
__global__ __launch_bounds__(128) void gemm_tc(const float* __restrict__ A,
                                               const float* __restrict__ B,
                                               const float* __restrict__ bias,
                                               float* __restrict__ C,
                                               int M, int Nn, int K) {
    __shared__ __align__(16) float As[2 * GA_BUF];
    __shared__ __align__(16) float Bs[2 * GB_BUF];
    int tid = threadIdx.x, lane = tid & 31, warp = tid >> 5;
    int n0 = blockIdx.x * 128, m0 = blockIdx.y * 128;
    int wm = (warp >> 1) * 64, wn = (warp & 1) * 64;

    GemmFrag F;
    gemm_mainloop(A, B, Nn, K, m0, n0, tid, lane, wm, wn,
                  As, Bs, smem_u32(As), smem_u32(Bs), F);

#pragma unroll
    for (int mt = 0; mt < 4; mt++) {
#pragma unroll
        for (int rr = 0; rr < 2; rr++) {
            int m = m0 + wm + mt * 16 + (lane >> 2) + rr * 8;
            float bv = bias[m];
#pragma unroll
            for (int nt = 0; nt < 8; nt++) {
                float v0 = F.acc[mt][nt][rr * 2 + 0] + bv;
                float v1 = F.acc[mt][nt][rr * 2 + 1] + bv;
                if (OUTMODE == 3) { v0 = rna_tf32(v0); v1 = rna_tf32(v1); }
                int n = n0 + wn + nt * 8 + 2 * (lane & 3);
                float2 st = make_float2(v0, v1);
                *(float2*)&C[(size_t)m * Nn + n] = st;
            }
        }
    }
}

// merged QKV: grid.z = 0/1/2 -> Q/K/V, bf16 permuted output [h][n][d]
__global__ __launch_bounds__(128) void qkv_tc(const float* __restrict__ Wbuf,
                                              const float* __restrict__ B,
                                              const float* __restrict__ bq,
                                              const float* __restrict__ bk,
                                              const float* __restrict__ bv,
                                              __nv_bfloat16* __restrict__ Qo,
                                              __nv_bfloat16* __restrict__ Ko,
                                              __nv_bfloat16* __restrict__ Vo) {
    __shared__ __align__(16) float As[2 * GA_BUF];
    __shared__ __align__(16) float Bs[2 * GB_BUF];
    int tid = threadIdx.x, lane = tid & 31, warp = tid >> 5;
    int n0 = blockIdx.x * 128, m0 = blockIdx.y * 128;
    int wm = (warp >> 1) * 64, wn = (warp & 1) * 64;
    int z = blockIdx.z;

    const float* A = Wbuf + (z == 0 ? WOFF_Q : (z == 1 ? WOFF_K : WOFF_V));
    const float* bias = (z == 0 ? bq : (z == 1 ? bk : bv));
    __nv_bfloat16* out = (z == 0 ? Qo : (z == 1 ? Ko : Vo));
    float scale = (z == 0) ? LG2E_D8 : 1.f;

    GemmFrag F;
    gemm_mainloop(A, B, AN, AC, m0, n0, tid, lane, wm, wn,
                  As, Bs, smem_u32(As), smem_u32(Bs), F);

#pragma unroll
    for (int mt = 0; mt < 4; mt++) {
#pragma unroll
        for (int rr = 0; rr < 2; rr++) {
            int m = m0 + wm + mt * 16 + (lane >> 2) + rr * 8;
            float bvv = bias[m];
            __nv_bfloat16* ob = out + (size_t)(m & 3) * ((size_t)AN * AD) + (m >> 2);
#pragma unroll
            for (int nt = 0; nt < 8; nt++) {
                int n = n0 + wn + nt * 8 + 2 * (lane & 3);
                ob[(size_t)n * AD] = __float2bfloat16((F.acc[mt][nt][rr * 2 + 0] + bvv) * scale);
                ob[(size_t)(n + 1) * AD] = __float2bfloat16((F.acc[mt][nt][rr * 2 + 1] + bvv) * scale);
            }
        }
    }
}

// ---------------- tensor-core flash attention (round-5, proven) ----------------
#define KSTRIDE 72
#define KSTRIDE_B 144
#define TILE_E (64 * KSTRIDE)

__global__ __launch_bounds__(128, 4) void attn_k(const __nv_bfloat16* __restrict__ Qp,
                                                 const __nv_bfloat16* __restrict__ Kp,
                                                 const __nv_bfloat16* __restrict__ Vp,
                                                 float* __restrict__ Msg) {
    __shared__ __align__(16) __nv_bfloat16 Qs[TILE_E];
    __shared__ __align__(16) __nv_bfloat16 Ks[2][TILE_E];
    __shared__ __align__(16) __nv_bfloat16 Vs[2][TILE_E];

    const int tid = threadIdx.x;
    const int lane = tid & 31, warp = tid >> 5;
    const int h = blockIdx.y;
    const int n0 = blockIdx.x * 64;
    const int m0w = warp * 16;

    const __nv_bfloat16* Qg = Qp + ((size_t)h * AN + n0) * AD;
    const __nv_bfloat16* Kg = Kp + (size_t)h * AN * AD;
    const __nv_bfloat16* Vg = Vp + (size_t)h * AN * AD;

    u32 qb = smem_u32(Qs);
    u32 kb0 = smem_u32(Ks);
    u32 vb0 = smem_u32(Vs);

    int lrow[4], lcol[4];
#pragma unroll
    for (int r = 0; r < 4; r++) {
        int c = tid + 128 * r;
        lrow[r] = c >> 3;
        lcol[r] = c & 7;
    }

#pragma unroll
    for (int r = 0; r < 4; r++) {
        u32 so = lrow[r] * KSTRIDE_B + lcol[r] * 16;
        size_t go = (size_t)lrow[r] * AD + lcol[r] * 8;
        CPASYNC16(qb + so, Qg + go);
        CPASYNC16(kb0 + so, Kg + go);
        CPASYNC16(vb0 + so, Vg + go);
    }
    CPASYNC_COMMIT();
#pragma unroll
    for (int r = 0; r < 4; r++) {
        u32 so = TILE_E * 2 + lrow[r] * KSTRIDE_B + lcol[r] * 16;
        size_t go = (size_t)(64 + lrow[r]) * AD + lcol[r] * 8;
        CPASYNC16(kb0 + so, Kg + go);
        CPASYNC16(vb0 + so, Vg + go);
    }
    CPASYNC_COMMIT();
    asm volatile("cp.async.wait_group 1;" ::: "memory");
    __syncthreads();

    u32 qa[4][4];
    {
        u32 qaddr = qb + (m0w + (lane & 15)) * KSTRIDE_B + (lane >> 4) * 16;
#pragma unroll
        for (int kk = 0; kk < 4; kk++)
            ldsm_x4(qaddr + kk * 32, qa[kk][0], qa[kk][1], qa[kk][2], qa[kk][3]);
    }

    float O[8][4];
#pragma unroll
    for (int t = 0; t < 8; t++) { O[t][0] = O[t][1] = O[t][2] = O[t][3] = 0.f; }
    float rs0 = 0.f, rs1 = 0.f;

    const u32 kfb = (lane & 7) * KSTRIDE_B + ((lane >> 3) & 1) * 16;
    const u32 vfb = ((lane & 7) + ((lane >> 3) & 1) * 8) * KSTRIDE_B;

    const int nIter = AN / 64;
    for (int it = 0; it < nIter; it++) {
        u32 kb = kb0 + (u32)(it & 1) * (TILE_E * 2);
        u32 vb = vb0 + (u32)(it & 1) * (TILE_E * 2);

        float S[8][4];
#pragma unroll
        for (int t = 0; t < 8; t++) { S[t][0] = S[t][1] = S[t][2] = S[t][3] = 0.f; }
#pragma unroll
        for (int kk = 0; kk < 4; kk++) {
#pragma unroll
            for (int t = 0; t < 8; t++) {
                u32 b0, b1;
                ldsm_x2(kb + kfb + t * (8 * KSTRIDE_B) + kk * 32, b0, b1);
                mma_bf16(S[t], qa[kk], b0, b1);
            }
        }
        u32 pa[4][4];
#pragma unroll
        for (int t = 0; t < 8; t += 2) {
#pragma unroll
            for (int e = 0; e < 4; e++) {
                S[t][e] = ex2(S[t][e]);
                S[t + 1][e] = ex2(S[t + 1][e]);
            }
            rs0 += (S[t][0] + S[t][1]) + (S[t + 1][0] + S[t + 1][1]);
            rs1 += (S[t][2] + S[t][3]) + (S[t + 1][2] + S[t + 1][3]);
            int kk2 = t >> 1;
            pa[kk2][0] = cvtbf2(S[t][1], S[t][0]);
            pa[kk2][1] = cvtbf2(S[t][3], S[t][2]);
            pa[kk2][2] = cvtbf2(S[t + 1][1], S[t + 1][0]);
            pa[kk2][3] = cvtbf2(S[t + 1][3], S[t + 1][2]);
        }
#pragma unroll
        for (int kk2 = 0; kk2 < 4; kk2++) {
#pragma unroll
            for (int t = 0; t < 8; t++) {
                u32 b0, b1;
                ldsm_x2t(vb + vfb + kk2 * (16 * KSTRIDE_B) + t * 16, b0, b1);
                mma_bf16(O[t], pa[kk2], b0, b1);
            }
        }

        __syncthreads();
        if (it + 2 < nIter) {
            int m0 = (it + 2) * 64;
            u32 kbn = kb0 + (u32)(it & 1) * (TILE_E * 2);
            u32 vbn = vb0 + (u32)(it & 1) * (TILE_E * 2);
#pragma unroll
            for (int r = 0; r < 4; r++) {
                u32 so = lrow[r] * KSTRIDE_B + lcol[r] * 16;
                size_t go = (size_t)(m0 + lrow[r]) * AD + lcol[r] * 8;
                CPASYNC16(kbn + so, Kg + go);
                CPASYNC16(vbn + so, Vg + go);
            }
            CPASYNC_COMMIT();
        }
        asm volatile("cp.async.wait_group 1;" ::: "memory");
        __syncthreads();
    }

    rs0 += __shfl_xor_sync(0xffffffffu, rs0, 1);
    rs0 += __shfl_xor_sync(0xffffffffu, rs0, 2);
    rs1 += __shfl_xor_sync(0xffffffffu, rs1, 1);
    rs1 += __shfl_xor_sync(0xffffffffu, rs1, 2);
    float inv0 = 1.f / rs0, inv1 = 1.f / rs1;

    int r0 = n0 + m0w + (lane >> 2);
    int r1 = r0 + 8;
    float* mbase = Msg + (size_t)h * AN;
#pragma unroll
    for (int t = 0; t < 8; t++) {
        int d0 = t * 8 + (lane & 3) * 2;
        mbase[(size_t)(4 * d0) * AN + r0] = rna_tf32(O[t][0] * inv0);
        mbase[(size_t)(4 * (d0 + 1)) * AN + r0] = rna_tf32(O[t][1] * inv0);
        mbase[(size_t)(4 * d0) * AN + r1] = rna_tf32(O[t][2] * inv1);
        mbase[(size_t)(4 * (d0 + 1)) * AN + r1] = rna_tf32(O[t][3] * inv1);
    }
}

// ---------------- InstanceNorm (biased var) + ReLU, rounded output ----------------
__global__ __launch_bounds__(256) void inorm_relu(float* __restrict__ Y) {
    const int Nn = AN;
    float* row = Y + (size_t)blockIdx.x * Nn;
    __shared__ float red[256];
    int tid = threadIdx.x;

    float s = 0.f;
    for (int i = tid; i < Nn; i += 256) s += row[i];
    red[tid] = s;
    __syncthreads();
    for (int off = 128; off > 0; off >>= 1) {
        if (tid < off) red[tid] += red[tid + off];
        __syncthreads();
    }
    float mean = red[0] * (1.f / Nn);
    __syncthreads();

    float ss = 0.f;
    for (int i = tid; i < Nn; i += 256) {
        float d = row[i] - mean;
        ss += d * d;
    }
    red[tid] = ss;
    __syncthreads();
    for (int off = 128; off > 0; off >>= 1) {
        if (tid < off) red[tid] += red[tid + off];
        __syncthreads();
    }
    float rstd = rsqrtf(red[0] * (1.f / Nn) + 1e-5f);

    for (int i = tid; i < Nn; i += 256) {
        float v = (row[i] - mean) * rstd;
        row[i] = rna_tf32(v > 0.f ? v : 0.f);
    }
}

// ---------------- launch ----------------
extern "C" void kernel_launch(void* const* d_in, const int* in_sizes, int n_in,
                              void* d_out, int out_size) {
    const float* descs = (const float*)d_in[0];
    const float* Wq = (const float*)d_in[1];
    const float* bq = (const float*)d_in[2];
    const float* Wk = (const float*)d_in[3];
    const float* bk = (const float*)d_in[4];
    const float* Wv = (const float*)d_in[5];
    const float* bv = (const float*)d_in[6];
    const float* Wm = (const float*)d_in[7];
    const float* bm = (const float*)d_in[8];
    const float* W1 = (const float*)d_in[9];
    const float* b1 = (const float*)d_in[10];
    const float* W2 = (const float*)d_in[11];
    const float* b2 = (const float*)d_in[12];
    float* out = (float*)d_out;

    float *xm, *msg, *y, *z, *wbuf;
    __nv_bfloat16 *qb, *kb, *vb;
    cudaGetSymbolAddress((void**)&xm, g_XM);
    cudaGetSymbolAddress((void**)&qb, g_Qb);
    cudaGetSymbolAddress((void**)&kb, g_Kb);
    cudaGetSymbolAddress((void**)&vb, g_Vb);
    cudaGetSymbolAddress((void**)&msg, g_Msg);
    cudaGetSymbolAddress((void**)&y, g_Y);
    cudaGetSymbolAddress((void**)&z, g_Z);
    cudaGetSymbolAddress((void**)&wbuf, g_Wbuf);

    dim3 tb(32, 8);

    preround_w<<<256, 256>>>(Wq, Wk, Wv, Wm, W1, W2, wbuf);
    transpose_in<<<dim3(AN / 32, AC / 32), tb>>>(descs, xm);

    qkv_tc<<<dim3(AN / 128, AC / 128, 3), 128>>>(wbuf, xm, bq, bk, bv, qb, kb, vb);

    attn_k<<<dim3(AN / 64, AH), 128>>>(qb, kb, vb, msg);

    gemm_tc<3><<<dim3(AN / 128, AC / 128), 128>>>(wbuf + WOFF_M, msg, bm,
                                                  xm + (size_t)AC * AN, AC, AN, AC);
    gemm_tc<0><<<dim3(AN / 128, AC2 / 128), 128>>>(wbuf + WOFF_1, xm, b1, y, AC2, AN, AC2);
    inorm_relu<<<AC2, 256>>>(y);
    gemm_tc<0><<<dim3(AN / 128, AC / 128), 128>>>(wbuf + WOFF_2, y, b2, z, AC, AN, AC2);

    transpose_add<<<dim3(AN / 32, AC / 32), tb>>>(descs, z, out);
}

// round 8
// speedup vs baseline: 11.4849x; 1.0092x over previous
#include <cuda_runtime.h>
#include <cuda_bf16.h>
#include <cstddef>

#define AN 8192          // sequence length
#define AC 256           // channels
#define AH 4             // heads
#define AD 64            // head dim
#define AC2 512          // 2*C
#define LG2E_D8 0.1803368801111601f   // log2(e)/8

typedef unsigned long long ull;
typedef unsigned int u32;

// ---------------- helpers ----------------
__device__ __forceinline__ float ex2(float x) {
    float y;
    asm("ex2.approx.f32 %0, %1;" : "=f"(y) : "f"(x));
    return y;
}
__device__ __forceinline__ float rna_tf32(float x) {
    u32 y;
    asm("cvt.rna.tf32.f32 %0, %1;" : "=r"(y) : "f"(x));
    return __uint_as_float(y);
}
__device__ __forceinline__ u32 smem_u32(const void* p) {
    u32 r;
    asm("{.reg .u64 t; cvta.to.shared.u64 t, %1; cvt.u32.u64 %0, t;}" : "=r"(r) : "l"(p));
    return r;
}
#define CPASYNC16(dst, src) \
    asm volatile("cp.async.cg.shared.global [%0], [%1], 16;" :: "r"(dst), "l"(src))
#define CPASYNC_COMMIT() asm volatile("cp.async.commit_group;" ::: "memory")
#define BAR_SYNC(id) asm volatile("bar.sync %0, 128;" :: "r"(id) : "memory")

// ---------------- mma / ldmatrix ----------------
__device__ __forceinline__ void ldsm_x4(u32 a, u32& r0, u32& r1, u32& r2, u32& r3) {
    asm volatile("ldmatrix.sync.aligned.m8n8.x4.shared.b16 {%0,%1,%2,%3}, [%4];"
                 : "=r"(r0), "=r"(r1), "=r"(r2), "=r"(r3) : "r"(a));
}
__device__ __forceinline__ void ldsm_x4t(u32 a, u32& r0, u32& r1, u32& r2, u32& r3) {
    asm volatile("ldmatrix.sync.aligned.m8n8.x4.trans.shared.b16 {%0,%1,%2,%3}, [%4];"
                 : "=r"(r0), "=r"(r1), "=r"(r2), "=r"(r3) : "r"(a));
}
__device__ __forceinline__ void mma_bf16(float* c, const u32* a, u32 b0, u32 b1) {
    asm volatile(
        "mma.sync.aligned.m16n8k16.row.col.f32.bf16.bf16.f32 "
        "{%0,%1,%2,%3}, {%4,%5,%6,%7}, {%8,%9}, {%0,%1,%2,%3};"
        : "+f"(c[0]), "+f"(c[1]), "+f"(c[2]), "+f"(c[3])
        : "r"(a[0]), "r"(a[1]), "r"(a[2]), "r"(a[3]), "r"(b0), "r"(b1));
}
__device__ __forceinline__ void mma_tf32(float* c, const u32* a, u32 b0, u32 b1) {
    asm volatile(
        "mma.sync.aligned.m16n8k8.row.col.f32.tf32.tf32.f32 "
        "{%0,%1,%2,%3}, {%4,%5,%6,%7}, {%8,%9}, {%0,%1,%2,%3};"
        : "+f"(c[0]), "+f"(c[1]), "+f"(c[2]), "+f"(c[3])
        : "r"(a[0]), "r"(a[1]), "r"(a[2]), "r"(a[3]), "r"(b0), "r"(b1));
}
__device__ __forceinline__ u32 cvtbf2(float hi, float lo) {
    u32 d;
    asm("cvt.rn.bf16x2.f32 %0, %1, %2;" : "=r"(d) : "f"(hi), "f"(lo));
    return d;
}

// ---------------- scratch (allocation-free, device globals) ----------------
__device__ float g_XM[(size_t)AC2 * AN];
__device__ __nv_bfloat16 g_Qb[(size_t)AH * AN * AD];
__device__ __nv_bfloat16 g_Kb[(size_t)AH * AN * AD];
__device__ __nv_bfloat16 g_Vb[(size_t)AH * AN * AD];
__device__ float g_Msg[(size_t)AC * AN];
__device__ float g_Y[(size_t)AC2 * AN];
__device__ float g_Z[(size_t)AC * AN];
#define WOFF_Q 0
#define WOFF_K 65536
#define WOFF_V 131072
#define WOFF_M 196608
#define WOFF_1 262144
#define WOFF_2 524288
#define WTOT   655360
__device__ float g_Wbuf[WTOT];

// ---------------- weight preround to tf32 (rna) ----------------
__global__ __launch_bounds__(256) void preround_w(const float* __restrict__ wq,
                                                  const float* __restrict__ wk,
                                                  const float* __restrict__ wv,
                                                  const float* __restrict__ wm,
                                                  const float* __restrict__ w1,
                                                  const float* __restrict__ w2,
                                                  float* __restrict__ dst) {
    for (int i = blockIdx.x * 256 + threadIdx.x; i < WTOT; i += gridDim.x * 256) {
        float v;
        if (i < WOFF_K) v = wq[i];
        else if (i < WOFF_V) v = wk[i - WOFF_K];
        else if (i < WOFF_M) v = wv[i - WOFF_V];
        else if (i < WOFF_1) v = wm[i - WOFF_M];
        else if (i < WOFF_2) v = w1[i - WOFF_1];
        else v = w2[i - WOFF_2];
        dst[i] = rna_tf32(v);
    }
}

// ---------------- transpose: X[c][n] = rna(descs[n][c]) ----------------
__global__ __launch_bounds__(256) void transpose_in(const float* __restrict__ descs,
                                                    float* __restrict__ X) {
    __shared__ float tile[32][33];
    int n0 = blockIdx.x * 32, c0 = blockIdx.y * 32;
    int tx = threadIdx.x, ty = threadIdx.y;
#pragma unroll
    for (int r = 0; r < 4; r++) {
        int n = n0 + ty + r * 8;
        tile[ty + r * 8][tx] = descs[(size_t)n * AC + c0 + tx];
    }
    __syncthreads();
#pragma unroll
    for (int r = 0; r < 4; r++) {
        int c = c0 + ty + r * 8;
        X[(size_t)c * AN + n0 + tx] = rna_tf32(tile[tx][ty + r * 8]);
    }
}

// ---------------- out[n][c] = descs[n][c] + Z[c][n] ----------------
__global__ __launch_bounds__(256) void transpose_add(const float* __restrict__ descs,
                                                     const float* __restrict__ Z,
                                                     float* __restrict__ out) {
    __shared__ float tile[32][33];
    int n0 = blockIdx.x * 32, c0 = blockIdx.y * 32;
    int tx = threadIdx.x, ty = threadIdx.y;
#pragma unroll
    for (int r = 0; r < 4; r++) {
        int c = c0 + ty + r * 8;
        tile[ty + r * 8][tx] = Z[(size_t)c * AN + n0 + tx];
    }
    __syncthreads();
#pragma unroll
    for (int r = 0; r < 4; r++) {
        int n = n0 + ty + r * 8;
        size_t idx = (size_t)n * AC + c0 + tx;
        out[idx] = descs[idx] + tile[tx][ty + r * 8];
    }
}

// ================= tf32 tensor-core GEMM (proven round-6) =================
#define GA_STRIDE 20
#define GA_BUF (128 * GA_STRIDE)
#define GB_BUF (16 * 128)

struct GemmFrag {
    float acc[4][8][4];
};

__device__ __forceinline__ void gemm_load_stage(const float* __restrict__ A,
                                                const float* __restrict__ B,
                                                int Nn, int K, int m0, int n0,
                                                int tid, int s, int k0,
                                                u32 asb, u32 bsb) {
    u32 ad = asb + (u32)s * (GA_BUF * 4) + (u32)(tid * GA_STRIDE) * 4;
    const float* ag = A + (size_t)(m0 + tid) * K + k0;
#pragma unroll
    for (int j = 0; j < 4; j++) CPASYNC16(ad + j * 16, ag + j * 4);
    int kr = tid >> 3;
    int cb = (tid & 7) * 16;
    u32 bd = bsb + (u32)s * (GB_BUF * 4) + (u32)(kr * 128) * 4;
    const float* bg = B + (size_t)(k0 + kr) * Nn + n0 + cb;
#pragma unroll
    for (int j = 0; j < 4; j++) {
        int pc = (cb + 4 * j) ^ ((kr & 3) << 3);
        CPASYNC16(bd + (u32)pc * 4, bg + 4 * j);
    }
}

__device__ __forceinline__ void gemm_mainloop(const float* __restrict__ A,
                                              const float* __restrict__ B,
                                              int Nn, int K, int m0, int n0,
                                              int tid, int lane, int wm, int wn,
                                              const float* As, const float* Bs,
                                              u32 asb, u32 bsb, GemmFrag& F) {
#pragma unroll
    for (int mt = 0; mt < 4; mt++)
#pragma unroll
        for (int nt = 0; nt < 8; nt++)
#pragma unroll
            for (int e = 0; e < 4; e++) F.acc[mt][nt][e] = 0.f;

    gemm_load_stage(A, B, Nn, K, m0, n0, tid, 0, 0, asb, bsb);
    CPASYNC_COMMIT();

    const int nIter = K >> 4;
    for (int it = 0; it < nIter; it++) {
        if (it + 1 < nIter) {
            gemm_load_stage(A, B, Nn, K, m0, n0, tid, (it + 1) & 1, (it + 1) * 16, asb, bsb);
            CPASYNC_COMMIT();
            asm volatile("cp.async.wait_group 1;" ::: "memory");
        } else {
            asm volatile("cp.async.wait_group 0;" ::: "memory");
        }
        __syncthreads();
        const float* as = As + (it & 1) * GA_BUF;
        const float* bs = Bs + (it & 1) * GB_BUF;
#pragma unroll
        for (int kk = 0; kk < 2; kk++) {
            u32 af[4][4];
            const int c = kk * 8 + (lane & 3);
#pragma unroll
            for (int mt = 0; mt < 4; mt++) {
                int r = wm + mt * 16 + (lane >> 2);
                af[mt][0] = __float_as_uint(as[r * GA_STRIDE + c]);
                af[mt][1] = __float_as_uint(as[(r + 8) * GA_STRIDE + c]);
                af[mt][2] = __float_as_uint(as[r * GA_STRIDE + c + 4]);
                af[mt][3] = __float_as_uint(as[(r + 8) * GA_STRIDE + c + 4]);
            }
#pragma unroll
            for (int nt = 0; nt < 8; nt++) {
                int nb = (wn + nt * 8 + (lane >> 2)) ^ ((lane & 3) << 3);
                u32 b0 = __float_as_uint(bs[c * 128 + nb]);
                u32 b1 = __float_as_uint(bs[(c + 4) * 128 + nb]);
#pragma unroll
                for (int mt = 0; mt < 4; mt++) mma_tf32(F.acc[mt][nt], af[mt], b0, b1);
            }
        }
        __syncthreads();
    }
}

template <int OUTMODE>
__global__ __launch_bounds__(128) void gemm_tc(const float* __restrict__ A,
                                               const float* __restrict__ B,
                                               const float* __restrict__ bias,
                                               float* __restrict__ C,
                                               int M, int Nn, int K) {
    __shared__ __align__(16) float As[2 * GA_BUF];
    __shared__ __align__(16) float Bs[2 * GB_BUF];
    int tid = threadIdx.x, lane = tid & 31, warp = tid >> 5;
    int n0 = blockIdx.x * 128, m0 = blockIdx.y * 128;
    int wm = (warp >> 1) * 64, wn = (warp & 1) * 64;

    GemmFrag F;
    gemm_mainloop(A, B, Nn, K, m0, n0, tid, lane, wm, wn,
                  As, Bs, smem_u32(As), smem_u32(Bs), F);

#pragma unroll
    for (int mt = 0; mt < 4; mt++) {
#pragma unroll
        for (int rr = 0; rr < 2; rr++) {
            int m = m0 + wm + mt * 16 + (lane >> 2) + rr * 8;
            float bv = bias[m];
#pragma unroll
            for (int nt = 0; nt < 8; nt++) {
                float v0 = F.acc[mt][nt][rr * 2 + 0] + bv;
                float v1 = F.acc[mt][nt][rr * 2 + 1] + bv;
                if (OUTMODE == 3) { v0 = rna_tf32(v0); v1 = rna_tf32(v1); }
                int n = n0 + wn + nt * 8 + 2 * (lane & 3);
                float2 st = make_float2(v0, v1);
                *(float2*)&C[(size_t)m * Nn + n] = st;
            }
        }
    }
}

__global__ __launch_bounds__(128) void qkv_tc(const float* __restrict__ Wbuf,
                                              const float* __restrict__ B,
                                              const float* __restrict__ bq,
                                              const float* __restrict__ bk,
                                              const float* __restrict__ bv,
                                              __nv_bfloat16* __restrict__ Qo,
                                              __nv_bfloat16* __restrict__ Ko,
                                              __nv_bfloat16* __restrict__ Vo) {
    __shared__ __align__(16) float As[2 * GA_BUF];
    __shared__ __align__(16) float Bs[2 * GB_BUF];
    int tid = threadIdx.x, lane = tid & 31, warp = tid >> 5;
    int n0 = blockIdx.x * 128, m0 = blockIdx.y * 128;
    int wm = (warp >> 1) * 64, wn = (warp & 1) * 64;
    int z = blockIdx.z;

    const float* A = Wbuf + (z == 0 ? WOFF_Q : (z == 1 ? WOFF_K : WOFF_V));
    const float* bias = (z == 0 ? bq : (z == 1 ? bk : bv));
    __nv_bfloat16* out = (z == 0 ? Qo : (z == 1 ? Ko : Vo));
    float scale = (z == 0) ? LG2E_D8 : 1.f;

    GemmFrag F;
    gemm_mainloop(A, B, AN, AC, m0, n0, tid, lane, wm, wn,
                  As, Bs, smem_u32(As), smem_u32(Bs), F);

#pragma unroll
    for (int mt = 0; mt < 4; mt++) {
#pragma unroll
        for (int rr = 0; rr < 2; rr++) {
            int m = m0 + wm + mt * 16 + (lane >> 2) + rr * 8;
            float bvv = bias[m];
            __nv_bfloat16* ob = out + (size_t)(m & 3) * ((size_t)AN * AD) + (m >> 2);
#pragma unroll
            for (int nt = 0; nt < 8; nt++) {
                int n = n0 + wn + nt * 8 + 2 * (lane & 3);
                ob[(size_t)n * AD] = __float2bfloat16((F.acc[mt][nt][rr * 2 + 0] + bvv) * scale);
                ob[(size_t)(n + 1) * AD] = __float2bfloat16((F.acc[mt][nt][rr * 2 + 1] + bvv) * scale);
            }
        }
    }
}

// ---------------- tensor-core flash attention, split-K dual warp-group ----------------
// 256 threads = 2 groups x 4 warps. 64 queries/block. Group g processes tiles 2j+g.
// Dynamic smem: Q (9216B) | K 4 tiles (36864B) | V 4 tiles (36864B) = 82944B.
#define KSTRIDE 72
#define KSTRIDE_B 144
#define TILE_E (64 * KSTRIDE)
#define TILE_B (TILE_E * 2)
#define ATTN_SMEM (TILE_B * 9)   // 9 tiles total = 82944 bytes

__global__ __launch_bounds__(256, 2) void attn_k(const __nv_bfloat16* __restrict__ Qp,
                                                 const __nv_bfloat16* __restrict__ Kp,
                                                 const __nv_bfloat16* __restrict__ Vp,
                                                 float* __restrict__ Msg) {
    extern __shared__ __align__(16) char dynsm[];
    __nv_bfloat16* Qs = (__nv_bfloat16*)dynsm;
    __nv_bfloat16* Ks = (__nv_bfloat16*)(dynsm + TILE_B);
    // Vs region begins at dynsm + TILE_B * 5

    const int tid = threadIdx.x;
    const int lane = tid & 31, warp = tid >> 5;
    const int group = warp >> 2;           // 0 or 1
    const int wid4 = warp & 3;
    const int gtid = tid & 127;
    const int h = blockIdx.y;
    const int n0 = blockIdx.x * 64;
    const int m0w = wid4 * 16;

    const __nv_bfloat16* Qg = Qp + ((size_t)h * AN + n0) * AD;
    const __nv_bfloat16* Kg = Kp + (size_t)h * AN * AD;
    const __nv_bfloat16* Vg = Vp + (size_t)h * AN * AD;

    u32 qb = smem_u32(Qs);
    u32 kb0 = qb + TILE_B + (u32)group * (2 * TILE_B);
    u32 vb0 = qb + TILE_B * 5 + (u32)group * (2 * TILE_B);

    // ---- prologue: Q (all threads) + this group's tiles j=0, j=1 ----
    {
        int c0 = tid, c1 = tid + 256;
        CPASYNC16(qb + (c0 >> 3) * KSTRIDE_B + (c0 & 7) * 16,
                  Qg + (size_t)(c0 >> 3) * AD + (c0 & 7) * 8);
        CPASYNC16(qb + (c1 >> 3) * KSTRIDE_B + (c1 & 7) * 16,
                  Qg + (size_t)(c1 >> 3) * AD + (c1 & 7) * 8);
        // tile j=0: key block index = group
        size_t tb = (size_t)(group * 64) * AD;
#pragma unroll
        for (int r = 0; r < 4; r++) {
            int c = gtid + 128 * r;
            u32 so = (c >> 3) * KSTRIDE_B + (c & 7) * 16;
            size_t go = tb + (size_t)(c >> 3) * AD + (c & 7) * 8;
            CPASYNC16(kb0 + so, Kg + go);
            CPASYNC16(vb0 + so, Vg + go);
        }
        CPASYNC_COMMIT();
        // tile j=1: key block index = 2 + group
        tb = (size_t)((2 + group) * 64) * AD;
#pragma unroll
        for (int r = 0; r < 4; r++) {
            int c = gtid + 128 * r;
            u32 so = TILE_B + (c >> 3) * KSTRIDE_B + (c & 7) * 16;
            size_t go = tb + (size_t)(c >> 3) * AD + (c & 7) * 8;
            CPASYNC16(kb0 + so, Kg + go);
            CPASYNC16(vb0 + so, Vg + go);
        }
        CPASYNC_COMMIT();
    }
    asm volatile("cp.async.wait_group 1;" ::: "memory");
    __syncthreads();   // Q + first tiles visible block-wide

    // Q a-fragments
    u32 qa[4][4];
    {
        u32 qaddr = qb + (m0w + (lane & 15)) * KSTRIDE_B + (lane >> 4) * 16;
#pragma unroll
        for (int kk = 0; kk < 4; kk++)
            ldsm_x4(qaddr + kk * 32, qa[kk][0], qa[kk][1], qa[kk][2], qa[kk][3]);
    }

    float O[8][4];
#pragma unroll
    for (int t = 0; t < 8; t++) { O[t][0] = O[t][1] = O[t][2] = O[t][3] = 0.f; }
    float rs0 = 0.f, rs1 = 0.f;

    const u32 kfb4 = (lane & 7) * KSTRIDE_B + ((lane >> 3) & 1) * 16 +
                     (lane >> 4) * (8 * KSTRIDE_B);
    const u32 vfb4 = ((lane & 7) + ((lane >> 3) & 1) * 8) * KSTRIDE_B +
                     (lane >> 4) * 16;
    const int barid = group + 1;

    const int nJ = (AN / 64) / 2;   // 64 tiles, 32 per group
    for (int j = 0; j < nJ; j++) {
        u32 kb = kb0 + (u32)(j & 1) * TILE_B;
        u32 vb = vb0 + (u32)(j & 1) * TILE_B;

        // ---- S = Q @ K^T ----
        float S[8][4];
#pragma unroll
        for (int t = 0; t < 8; t++) { S[t][0] = S[t][1] = S[t][2] = S[t][3] = 0.f; }
#pragma unroll
        for (int kk = 0; kk < 4; kk++) {
#pragma unroll
            for (int t2 = 0; t2 < 4; t2++) {
                u32 b0, b1, b2, b3;
                ldsm_x4(kb + kfb4 + t2 * (16 * KSTRIDE_B) + kk * 32, b0, b1, b2, b3);
                mma_bf16(S[2 * t2], qa[kk], b0, b1);
                mma_bf16(S[2 * t2 + 1], qa[kk], b2, b3);
            }
        }
        // ---- exp2 + pack P ----
        u32 pa[4][4];
#pragma unroll
        for (int t = 0; t < 8; t += 2) {
#pragma unroll
            for (int e = 0; e < 4; e++) {
                S[t][e] = ex2(S[t][e]);
                S[t + 1][e] = ex2(S[t + 1][e]);
            }
            rs0 += (S[t][0] + S[t][1]) + (S[t + 1][0] + S[t + 1][1]);
            rs1 += (S[t][2] + S[t][3]) + (S[t + 1][2] + S[t + 1][3]);
            int kk2 = t >> 1;
            pa[kk2][0] = cvtbf2(S[t][1], S[t][0]);
            pa[kk2][1] = cvtbf2(S[t][3], S[t][2]);
            pa[kk2][2] = cvtbf2(S[t + 1][1], S[t + 1][0]);
            pa[kk2][3] = cvtbf2(S[t + 1][3], S[t + 1][2]);
        }
        // ---- O += P @ V ----
#pragma unroll
        for (int kk2 = 0; kk2 < 4; kk2++) {
#pragma unroll
            for (int t2 = 0; t2 < 4; t2++) {
                u32 b0, b1, b2, b3;
                ldsm_x4t(vb + vfb4 + kk2 * (16 * KSTRIDE_B) + t2 * 32, b0, b1, b2, b3);
                mma_bf16(O[2 * t2], pa[kk2], b0, b1);
                mma_bf16(O[2 * t2 + 1], pa[kk2], b2, b3);
            }
        }

        BAR_SYNC(barid);   // group done reading buf (j&1)
        if (j + 2 < nJ) {
            size_t tb = (size_t)((2 * (j + 2) + group) * 64) * AD;
            u32 kbn = kb0 + (u32)(j & 1) * TILE_B;
            u32 vbn = vb0 + (u32)(j & 1) * TILE_B;
#pragma unroll
            for (int r = 0; r < 4; r++) {
                int c = gtid + 128 * r;
                u32 so = (c >> 3) * KSTRIDE_B + (c & 7) * 16;
                size_t go = tb + (size_t)(c >> 3) * AD + (c & 7) * 8;
                CPASYNC16(kbn + so, Kg + go);
                CPASYNC16(vbn + so, Vg + go);
            }
            CPASYNC_COMMIT();
            asm volatile("cp.async.wait_group 1;" ::: "memory");
        } else {
            asm volatile("cp.async.wait_group 0;" ::: "memory");
        }
        BAR_SYNC(barid);   // next buffer visible to group
    }

    // ---- combine groups: group1 -> smem -> group0 adds ----
    __syncthreads();
    float* ex = (float*)Ks;   // reuse K region (36.8KB >= 128*35*4)
    if (group == 1) {
        float* s = ex + gtid * 35;
#pragma unroll
        for (int t = 0; t < 8; t++) {
            s[4 * t + 0] = O[t][0]; s[4 * t + 1] = O[t][1];
            s[4 * t + 2] = O[t][2]; s[4 * t + 3] = O[t][3];
        }
        s[32] = rs0;
        s[33] = rs1;
    }
    __syncthreads();
    if (group == 0) {
        const float* s = ex + gtid * 35;
#pragma unroll
        for (int t = 0; t < 8; t++) {
            O[t][0] += s[4 * t + 0]; O[t][1] += s[4 * t + 1];
            O[t][2] += s[4 * t + 2]; O[t][3] += s[4 * t + 3];
        }
        rs0 += s[32];
        rs1 += s[33];

        rs0 += __shfl_xor_sync(0xffffffffu, rs0, 1);
        rs0 += __shfl_xor_sync(0xffffffffu, rs0, 2);
        rs1 += __shfl_xor_sync(0xffffffffu, rs1, 1);
        rs1 += __shfl_xor_sync(0xffffffffu, rs1, 2);
        float inv0 = 1.f / rs0, inv1 = 1.f / rs1;

        int r0 = n0 + m0w + (lane >> 2);
        int r1 = r0 + 8;
        float* mbase = Msg + (size_t)h * AN;
#pragma unroll
        for (int t = 0; t < 8; t++) {
            int d0 = t * 8 + (lane & 3) * 2;
            mbase[(size_t)(4 * d0) * AN + r0] = rna_tf32(O[t][0] * inv0);
            mbase[(size_t)(4 * (d0 + 1)) * AN + r0] = rna_tf32(O[t][1] * inv0);
            mbase[(size_t)(4 * d0) * AN + r1] = rna_tf32(O[t][2] * inv1);
            mbase[(size_t)(4 * (d0 + 1)) * AN + r1] = rna_tf32(O[t][3] * inv1);
        }
    }
}

// ---------------- InstanceNorm (biased var) + ReLU, rounded output ----------------
__global__ __launch_bounds__(256) void inorm_relu(float* __restrict__ Y) {
    const int Nn = AN;
    float* row = Y + (size_t)blockIdx.x * Nn;
    __shared__ float red[256];
    int tid = threadIdx.x;

    float s = 0.f;
    for (int i = tid; i < Nn; i += 256) s += row[i];
    red[tid] = s;
    __syncthreads();
    for (int off = 128; off > 0; off >>= 1) {
        if (tid < off) red[tid] += red[tid + off];
        __syncthreads();
    }
    float mean = red[0] * (1.f / Nn);
    __syncthreads();

    float ss = 0.f;
    for (int i = tid; i < Nn; i += 256) {
        float d = row[i] - mean;
        ss += d * d;
    }
    red[tid] = ss;
    __syncthreads();
    for (int off = 128; off > 0; off >>= 1) {
        if (tid < off) red[tid] += red[tid + off];
        __syncthreads();
    }
    float rstd = rsqrtf(red[0] * (1.f / Nn) + 1e-5f);

    for (int i = tid; i < Nn; i += 256) {
        float v = (row[i] - mean) * rstd;
        row[i] = rna_tf32(v > 0.f ? v : 0.f);
    }
}

// ---------------- launch ----------------
extern "C" void kernel_launch(void* const* d_in, const int* in_sizes, int n_in,
                              void* d_out, int out_size) {
    const float* descs = (const float*)d_in[0];
    const float* Wq = (const float*)d_in[1];
    const float* bq = (const float*)d_in[2];
    const float* Wk = (const float*)d_in[3];
    const float* bk = (const float*)d_in[4];
    const float* Wv = (const float*)d_in[5];
    const float* bv = (const float*)d_in[6];
    const float* Wm = (const float*)d_in[7];
    const float* bm = (const float*)d_in[8];
    const float* W1 = (const float*)d_in[9];
    const float* b1 = (const float*)d_in[10];
    const float* W2 = (const float*)d_in[11];
    const float* b2 = (const float*)d_in[12];
    float* out = (float*)d_out;

    float *xm, *msg, *y, *z, *wbuf;
    __nv_bfloat16 *qb, *kb, *vb;
    cudaGetSymbolAddress((void**)&xm, g_XM);
    cudaGetSymbolAddress((void**)&qb, g_Qb);
    cudaGetSymbolAddress((void**)&kb, g_Kb);
    cudaGetSymbolAddress((void**)&vb, g_Vb);
    cudaGetSymbolAddress((void**)&msg, g_Msg);
    cudaGetSymbolAddress((void**)&y, g_Y);
    cudaGetSymbolAddress((void**)&z, g_Z);
    cudaGetSymbolAddress((void**)&wbuf, g_Wbuf);

    cudaFuncSetAttribute(attn_k, cudaFuncAttributeMaxDynamicSharedMemorySize, ATTN_SMEM);

    dim3 tb(32, 8);

    preround_w<<<256, 256>>>(Wq, Wk, Wv, Wm, W1, W2, wbuf);
    transpose_in<<<dim3(AN / 32, AC / 32), tb>>>(descs, xm);

    qkv_tc<<<dim3(AN / 128, AC / 128, 3), 128>>>(wbuf, xm, bq, bk, bv, qb, kb, vb);

    attn_k<<<dim3(AN / 64, AH), 256, ATTN_SMEM>>>(qb, kb, vb, msg);

    gemm_tc<3><<<dim3(AN / 128, AC / 128), 128>>>(wbuf + WOFF_M, msg, bm,
                                                  xm + (size_t)AC * AN, AC, AN, AC);
    gemm_tc<0><<<dim3(AN / 128, AC2 / 128), 128>>>(wbuf + WOFF_1, xm, b1, y, AC2, AN, AC2);
    inorm_relu<<<AC2, 256>>>(y);
    gemm_tc<0><<<dim3(AN / 128, AC / 128), 128>>>(wbuf + WOFF_2, y, b2, z, AC, AN, AC2);

    transpose_add<<<dim3(AN / 32, AC / 32), tb>>>(descs, z, out);
}